// round 15
// baseline (speedup 1.0000x reference)
#include <cuda_runtime.h>
#include <cuda_fp16.h>
#include <cstdint>
#include <math.h>

// Router: logits = x @ W^T (N=16384, D=2048, E=64), softmax, top-2, renorm.
// Output fp32 concat: probs [N*64] | indices [N*2] | weights [N*2]
//
// R15: register-direct GEMM. prep writes x as fp16 MMA fragments in
// per-lane order (g_A: [warp_tile 512][kstep 128][lane 32][8 u32]) and W
// as fragment-ordered g_Bf (256 KB, L2-resident). The router mainloop is
// pure LDG -> mma.sync: 2x LDG.128 (A) + 2x LDG.64 (B) + 4 HMMA per
// kstep per warp. NO smem staging, NO mbarriers, NO barriers in the
// mainloop; free-running warps at 3 CTA/SM. Numerics identical to R14
// (fp16 x and W, 128-k local fold, inline exact-fp32 refine).

#define D_DIM 2048
#define E_DIM 64
#define BM 64
#define THREADS 256
#define N_ROWS 16384
#define NBLK (N_ROWS / BM)     // 256
#define NWT (N_ROWS / 32)      // 512 warp tiles
#define NKS (D_DIM / 16)       // 128 ksteps
#define TAU 2e-3f

// g_A[wt][k][lane][8 u32]  = 512*128*32*8*4 B = 64 MB
__device__ uint32_t g_A[(size_t)NWT * NKS * 32 * 8];
// g_Bf[k][ng(8)][lane][2 u32] = 128*8*32*8 B = 256 KB
__device__ uint2 g_Bf[NKS * 8 * 32];

__device__ __forceinline__ uint32_t h2pack(float a, float b) {
    __half2 h = __floats2half2_rn(a, b);
    return *(uint32_t*)&h;
}
__device__ __forceinline__ void mma_f16(float* c,
                                        uint32_t a0, uint32_t a1, uint32_t a2, uint32_t a3,
                                        uint32_t b0, uint32_t b1) {
    asm volatile(
        "mma.sync.aligned.m16n8k16.row.col.f32.f16.f16.f32 "
        "{%0,%1,%2,%3}, {%4,%5,%6,%7}, {%8,%9}, {%0,%1,%2,%3};"
        : "+f"(c[0]), "+f"(c[1]), "+f"(c[2]), "+f"(c[3])
        : "r"(a0), "r"(a1), "r"(a2), "r"(a3), "r"(b0), "r"(b1));
}

// ---- Kernel 1: prep. grid 8320 x 256 threads.
// Blocks 0..8191: one (warp_tile, kgroup-of-8) A-fragment blob each.
// Blocks 8192..8319: g_Bf (32768 thread-items).
__global__ __launch_bounds__(256, 3)
void prep_kernel(const float* __restrict__ x, const float* __restrict__ W)
{
    __shared__ float xs[32][136];
    const int b   = blockIdx.x;
    const int tid = threadIdx.x;

    if (b < NWT * 16) {
        const int wt = b >> 4;
        const int kg = b & 15;         // kgroup: ksteps kg*8 .. kg*8+7 (128 k cols)

        // load x tile 32 rows x 128 cols (coalesced float4)
#pragma unroll
        for (int i = 0; i < 4; i++) {
            int f  = tid + i * 256;
            int r  = f >> 5;
            int c4 = (f & 31) * 4;
            *(float4*)&xs[r][c4] =
                *(const float4*)(x + (size_t)(wt * 32 + r) * D_DIM + kg * 128 + c4);
        }
        __syncthreads();

        // emit fragments: thread = (kstep ks = tid>>5, lane)
        const int ks   = tid >> 5;
        const int lane = tid & 31;
        const int qr   = lane >> 2;
        const int qc   = lane & 3;
        const int kk   = ks * 16;

        uint32_t o[8];
#pragma unroll
        for (int mt = 0; mt < 2; mt++) {
            int r0 = mt * 16 + qr;
            o[mt * 4 + 0] = h2pack(xs[r0][kk + 2 * qc],     xs[r0][kk + 2 * qc + 1]);
            o[mt * 4 + 1] = h2pack(xs[r0 + 8][kk + 2 * qc], xs[r0 + 8][kk + 2 * qc + 1]);
            o[mt * 4 + 2] = h2pack(xs[r0][kk + 2 * qc + 8],     xs[r0][kk + 2 * qc + 9]);
            o[mt * 4 + 3] = h2pack(xs[r0 + 8][kk + 2 * qc + 8], xs[r0 + 8][kk + 2 * qc + 9]);
        }
        uint32_t* dst = g_A + (((size_t)wt * NKS + kg * 8 + ks) * 32 + lane) * 8;
        *(uint4*)(dst)     = make_uint4(o[0], o[1], o[2], o[3]);
        *(uint4*)(dst + 4) = make_uint4(o[4], o[5], o[6], o[7]);
    } else {
        // W fragments: item i = (kstep, ng, lane)
        const int i = (b - NWT * 16) * 256 + tid;   // 0..32767
        const int k    = i >> 8;
        const int rem  = i & 255;
        const int ng   = rem >> 5;
        const int lane = rem & 31;
        const int qr   = lane >> 2;
        const int qc   = lane & 3;
        const int e    = ng * 8 + qr;
        const float* w = W + (size_t)e * D_DIM + k * 16;
        uint2 v;
        v.x = h2pack(w[2 * qc],     w[2 * qc + 1]);
        v.y = h2pack(w[2 * qc + 8], w[2 * qc + 9]);
        g_Bf[(k * 8 + ng) * 32 + lane] = v;
    }
}

// ---- Kernel 2: router GEMM + softmax + top-2 (+ inline exact refine) ----
__global__ __launch_bounds__(THREADS, 3)
void router_kernel(const float* __restrict__ x,
                   const float* __restrict__ W,
                   float* __restrict__ probs_out,
                   float* __restrict__ idx_out,
                   float* __restrict__ w_out)
{
    __shared__ float ls[BM][E_DIM + 2];

    const int tid  = threadIdx.x;
    const int wid  = tid >> 5;
    const int lane = tid & 31;
    const int nb   = blockIdx.x;
    const int m0   = nb * BM;

    const int rb = wid >> 2;        // row band 0..1 (32 rows each)
    const int cg = wid & 3;         // col group 0..3 (16 experts each)
    const int qr = lane >> 2;
    const int qc = lane & 3;

    const int wt  = nb * 2 + rb;
    const int ng0 = cg * 2;

    const uint4* Ap = (const uint4*)g_A + (size_t)wt * NKS * 64 + lane * 2;
    const uint2* Bp = g_Bf + lane;

    float accM[2][2][4];
#pragma unroll
    for (int i = 0; i < 2; i++)
#pragma unroll
        for (int j = 0; j < 2; j++)
#pragma unroll
            for (int k = 0; k < 4; k++) accM[i][j][k] = 0.0f;

    for (int kb = 0; kb < NKS; kb += 8) {
        float accL[2][2][4];
#pragma unroll
        for (int i = 0; i < 2; i++)
#pragma unroll
            for (int j = 0; j < 2; j++)
#pragma unroll
                for (int k = 0; k < 4; k++) accL[i][j][k] = 0.0f;

#pragma unroll
        for (int kk = 0; kk < 8; kk++) {
            const int k = kb + kk;
            uint4 a0 = Ap[(size_t)k * 64];
            uint4 a1 = Ap[(size_t)k * 64 + 1];
            uint2 b0 = Bp[(k * 8 + ng0) * 32];
            uint2 b1 = Bp[(k * 8 + ng0 + 1) * 32];

            mma_f16(accL[0][0], a0.x, a0.y, a0.z, a0.w, b0.x, b0.y);
            mma_f16(accL[0][1], a0.x, a0.y, a0.z, a0.w, b1.x, b1.y);
            mma_f16(accL[1][0], a1.x, a1.y, a1.z, a1.w, b0.x, b0.y);
            mma_f16(accL[1][1], a1.x, a1.y, a1.z, a1.w, b1.x, b1.y);
        }

#pragma unroll
        for (int i = 0; i < 2; i++)
#pragma unroll
            for (int j = 0; j < 2; j++)
#pragma unroll
                for (int k = 0; k < 4; k++) accM[i][j][k] += accL[i][j][k];
    }

    // ---- stage logits into smem ----
#pragma unroll
    for (int mt = 0; mt < 2; mt++)
#pragma unroll
        for (int nt = 0; nt < 2; nt++) {
            int rr = rb * 32 + mt * 16 + qr;
            int cc = cg * 16 + nt * 8 + qc * 2;
            ls[rr][cc]         = accM[mt][nt][0];
            ls[rr][cc + 1]     = accM[mt][nt][1];
            ls[rr + 8][cc]     = accM[mt][nt][2];
            ls[rr + 8][cc + 1] = accM[mt][nt][3];
        }
    __syncthreads();

    // ---- epilogue: one warp per row (8 warps, 8 rows each) ----
    const unsigned FULL = 0xFFFFFFFFu;

    auto wtop2 = [&](float pa, int ia, float pb, int ib,
                     float& V1, int& I1, float& V2, int& I2) {
        float v1, v2; int i1, i2;
        if (pa >= pb) { v1 = pa; i1 = ia; v2 = pb; i2 = ib; }
        else          { v1 = pb; i1 = ib; v2 = pa; i2 = ia; }
#pragma unroll
        for (int off = 16; off > 0; off >>= 1) {
            float ov1 = __shfl_xor_sync(FULL, v1, off);
            int   oi1 = __shfl_xor_sync(FULL, i1, off);
            float ov2 = __shfl_xor_sync(FULL, v2, off);
            int   oi2 = __shfl_xor_sync(FULL, i2, off);
            bool o_first = (ov1 > v1) || (ov1 == v1 && oi1 < i1);
            float n1, n2; int ni1, ni2;
            if (o_first) {
                n1 = ov1; ni1 = oi1;
                bool aa = (v1 > ov2) || (v1 == ov2 && i1 < oi2);
                if (aa) { n2 = v1;  ni2 = i1;  } else { n2 = ov2; ni2 = oi2; }
            } else {
                n1 = v1; ni1 = i1;
                bool aa = (ov1 > v2) || (ov1 == v2 && oi1 < i2);
                if (aa) { n2 = ov1; ni2 = oi1; } else { n2 = v2;  ni2 = i2;  }
            }
            v1 = n1; i1 = ni1; v2 = n2; i2 = ni2;
        }
        V1 = v1; I1 = i1; V2 = v2; I2 = i2;
    };

    for (int rrow = wid; rrow < BM; rrow += 8) {
        float l1 = ls[rrow][lane];
        float l2 = ls[rrow][lane + 32];

        float m = fmaxf(l1, l2);
#pragma unroll
        for (int off = 16; off > 0; off >>= 1)
            m = fmaxf(m, __shfl_xor_sync(FULL, m, off));

        float e1 = expf(l1 - m);
        float e2 = expf(l2 - m);

        float s = e1 + e2;
#pragma unroll
        for (int off = 16; off > 0; off >>= 1)
            s += __shfl_xor_sync(FULL, s, off);
        float inv = 1.0f / s;

        float pa = e1 * inv;
        float pb = e2 * inv;

        const int row = m0 + rrow;
        probs_out[(size_t)row * E_DIM + lane]      = pa;
        probs_out[(size_t)row * E_DIM + lane + 32] = pb;

        float v1, v2, v3, v4;
        int i1, i2, i3, i4;
        wtop2(pa, lane, pb, lane + 32, v1, i1, v2, i2);

        float pa2 = (lane == i1 || lane == i2) ? -1.0f : pa;
        float pb2 = (lane + 32 == i1 || lane + 32 == i2) ? -1.0f : pb;
        wtop2(pa2, lane, pb2, lane + 32, v3, i3, v4, i4);

        bool ambiguous = ((v1 - v2) < TAU) || ((v2 - v3) < TAU);

        if (!ambiguous) {
            if (lane == 0) {
                float denom = v1 + v2 + 1e-9f;
                idx_out[(size_t)row * 2 + 0] = (float)i1;
                idx_out[(size_t)row * 2 + 1] = (float)i2;
                w_out[(size_t)row * 2 + 0]   = v1 / denom;
                w_out[(size_t)row * 2 + 1]   = v2 / denom;
            }
        } else {
            // inline exact fp32 recompute of 4 candidate logits
            const float* xr = x + (size_t)row * D_DIM;
            const float* w0 = W + (size_t)i1 * D_DIM;
            const float* w1 = W + (size_t)i2 * D_DIM;
            const float* w2 = W + (size_t)i3 * D_DIM;
            const float* w3 = W + (size_t)i4 * D_DIM;

            float d0 = 0.f, d1 = 0.f, d2 = 0.f, d3 = 0.f;
            for (int k = lane * 4; k < D_DIM; k += 128) {
                float4 xv = *(const float4*)(xr + k);
                float4 a  = *(const float4*)(w0 + k);
                float4 b  = *(const float4*)(w1 + k);
                float4 cc = *(const float4*)(w2 + k);
                float4 dd = *(const float4*)(w3 + k);
                d0 = fmaf(xv.x, a.x,  fmaf(xv.y, a.y,  fmaf(xv.z, a.z,  fmaf(xv.w, a.w,  d0))));
                d1 = fmaf(xv.x, b.x,  fmaf(xv.y, b.y,  fmaf(xv.z, b.z,  fmaf(xv.w, b.w,  d1))));
                d2 = fmaf(xv.x, cc.x, fmaf(xv.y, cc.y, fmaf(xv.z, cc.z, fmaf(xv.w, cc.w, d2))));
                d3 = fmaf(xv.x, dd.x, fmaf(xv.y, dd.y, fmaf(xv.z, dd.z, fmaf(xv.w, dd.w, d3))));
            }
#pragma unroll
            for (int off = 16; off > 0; off >>= 1) {
                d0 += __shfl_xor_sync(FULL, d0, off);
                d1 += __shfl_xor_sync(FULL, d1, off);
                d2 += __shfl_xor_sync(FULL, d2, off);
                d3 += __shfl_xor_sync(FULL, d3, off);
            }
            if (lane == 0) {
                float l[4]  = {d0, d1, d2, d3};
                int   id[4] = {i1, i2, i3, i4};
#pragma unroll
                for (int i = 0; i < 2; i++) {
                    int best = i;
#pragma unroll
                    for (int j = i + 1; j < 4; j++) {
                        if ((l[j] > l[best]) || (l[j] == l[best] && id[j] < id[best])) best = j;
                    }
                    float tl = l[i]; l[i] = l[best]; l[best] = tl;
                    int ti = id[i]; id[i] = id[best]; id[best] = ti;
                }
                float mm  = fmaxf(l[0], l[1]);
                float ee1 = expf(l[0] - mm);
                float ee2 = expf(l[1] - mm);
                float w1v = ee1 / (ee1 + ee2);
                idx_out[(size_t)row * 2 + 0] = (float)id[0];
                idx_out[(size_t)row * 2 + 1] = (float)id[1];
                w_out[(size_t)row * 2 + 0]   = w1v;
                w_out[(size_t)row * 2 + 1]   = 1.0f - w1v;
            }
        }
    }
}

extern "C" void kernel_launch(void* const* d_in, const int* in_sizes, int n_in,
                              void* d_out, int out_size)
{
    const float* x = (const float*)d_in[0];
    const float* W = (const float*)d_in[1];
    const int N = in_sizes[0] / D_DIM;   // 16384

    float* out   = (float*)d_out;
    float* probs = out;
    float* idx   = out + (size_t)N * E_DIM;
    float* wts   = out + (size_t)N * E_DIM + (size_t)N * 2;

    prep_kernel<<<NWT * 16 + 128, 256>>>(x, W);
    router_kernel<<<N / BM, THREADS>>>(x, W, probs, idx, wts);
}

// round 16
// speedup vs baseline: 1.2542x; 1.2542x over previous
#include <cuda_runtime.h>
#include <cuda_fp16.h>
#include <cstdint>
#include <math.h>

// Router: logits = x @ W^T (N=16384, D=2048, E=64), softmax, top-2, renorm.
// Output fp32 concat: probs [N*64] | indices [N*2] | weights [N*2]
//
// R16: fused single-pass GEMM. 512 independent warps (grid 512 x 32 thr,
// no smem, no barriers). Each warp owns a 32-row x 64-expert tile:
// reads x fp32 directly (sector-coalesced float2), converts to fp16
// fragments in registers, 16x m16n8k16 HMMA per kstep vs L2-resident
// pre-fragmented W (g_Bf). Register-only epilogue: quad-shuffle softmax
// + top-2 + ballot-compacted exact-fp32 refine. x is read exactly once.

#define D_DIM 2048
#define E_DIM 64
#define N_ROWS 16384
#define NKS (D_DIM / 16)       // 128 ksteps
#define NWT (N_ROWS / 32)      // 512 warp tiles
#define TAU 2e-3f

// g_Bf[k][ng(8)][lane(32)] : uint2 = 4 fp16 (validated R15 layout)
__device__ uint2 g_Bf[NKS * 8 * 32];

__device__ __forceinline__ uint32_t h2pack(float a, float b) {
    __half2 h = __floats2half2_rn(a, b);
    return *(uint32_t*)&h;
}
__device__ __forceinline__ void mma_f16(float* c,
                                        uint32_t a0, uint32_t a1, uint32_t a2, uint32_t a3,
                                        uint32_t b0, uint32_t b1) {
    asm volatile(
        "mma.sync.aligned.m16n8k16.row.col.f32.f16.f16.f32 "
        "{%0,%1,%2,%3}, {%4,%5,%6,%7}, {%8,%9}, {%0,%1,%2,%3};"
        : "+f"(c[0]), "+f"(c[1]), "+f"(c[2]), "+f"(c[3])
        : "r"(a0), "r"(a1), "r"(a2), "r"(a3), "r"(b0), "r"(b1));
}

// ---- Kernel 1: W -> fragment order (32768 items) ----
__global__ __launch_bounds__(256, 4)
void bprep_kernel(const float* __restrict__ W)
{
    const int i = blockIdx.x * 256 + threadIdx.x;   // 0..32767
    const int k    = i >> 8;
    const int rem  = i & 255;
    const int ng   = rem >> 5;
    const int lane = rem & 31;
    const int qr   = lane >> 2;
    const int qc   = lane & 3;
    const int e    = ng * 8 + qr;
    const float* w = W + (size_t)e * D_DIM + k * 16;
    uint2 v;
    v.x = h2pack(w[2 * qc],     w[2 * qc + 1]);
    v.y = h2pack(w[2 * qc + 8], w[2 * qc + 9]);
    g_Bf[(k * 8 + ng) * 32 + lane] = v;
}

// ---- Kernel 2: fused router ----
__global__ __launch_bounds__(32, 8)
void router_kernel(const float* __restrict__ x,
                   const float* __restrict__ W,
                   float* __restrict__ probs_out,
                   float* __restrict__ idx_out,
                   float* __restrict__ w_out)
{
    const int wt   = blockIdx.x;          // warp tile 0..511
    const int lane = threadIdx.x;
    const int qr   = lane >> 2;           // 0..7
    const int qc   = lane & 3;            // 0..3
    const unsigned FULL = 0xFFFFFFFFu;

    const int base = wt * 32;
    // row pointers for this lane: rows base+qr (+8, +16, +24), col offset 2*qc
    const float* xr = x + (size_t)(base + qr) * D_DIM + 2 * qc;

    float acc[2][8][4];
#pragma unroll
    for (int i = 0; i < 2; i++)
#pragma unroll
        for (int j = 0; j < 8; j++)
#pragma unroll
            for (int k = 0; k < 4; k++) acc[i][j][k] = 0.0f;

    const uint2* Bp = g_Bf + lane;

#pragma unroll 4
    for (int k = 0; k < NKS; k++) {
        const int ko = k * 16;

        // A fragments: 2 m-tiles, 8 float2 loads -> 8 packed u32
        uint32_t a[2][4];
#pragma unroll
        for (int mt = 0; mt < 2; mt++) {
            const float* p0 = xr + (size_t)mt * 16 * D_DIM + ko;
            const float* p1 = p0 + (size_t)8 * D_DIM;
            float2 f00 = *(const float2*)(p0);
            float2 f01 = *(const float2*)(p0 + 8);
            float2 f10 = *(const float2*)(p1);
            float2 f11 = *(const float2*)(p1 + 8);
            a[mt][0] = h2pack(f00.x, f00.y);
            a[mt][1] = h2pack(f10.x, f10.y);
            a[mt][2] = h2pack(f01.x, f01.y);
            a[mt][3] = h2pack(f11.x, f11.y);
        }

        // B fragments: 8 expert groups
        uint2 b[8];
#pragma unroll
        for (int ng = 0; ng < 8; ng++)
            b[ng] = __ldg(Bp + (size_t)(k * 8 + ng) * 32);

#pragma unroll
        for (int mt = 0; mt < 2; mt++)
#pragma unroll
            for (int ng = 0; ng < 8; ng++)
                mma_f16(acc[mt][ng], a[mt][0], a[mt][1], a[mt][2], a[mt][3],
                        b[ng].x, b[ng].y);
    }

    // ---- epilogue: 4 rows per lane, quad-level (shfl 1,2) reductions ----
#pragma unroll
    for (int mt = 0; mt < 2; mt++) {
#pragma unroll
        for (int half = 0; half < 2; half++) {
            const int row = base + mt * 16 + 8 * half + qr;

            float v[16];
#pragma unroll
            for (int ng = 0; ng < 8; ng++) {
                v[2 * ng]     = acc[mt][ng][2 * half];
                v[2 * ng + 1] = acc[mt][ng][2 * half + 1];
            }

            // softmax (quad reduction: lanes qr*4 .. qr*4+3 share a row)
            float m = v[0];
#pragma unroll
            for (int j = 1; j < 16; j++) m = fmaxf(m, v[j]);
            m = fmaxf(m, __shfl_xor_sync(FULL, m, 1));
            m = fmaxf(m, __shfl_xor_sync(FULL, m, 2));

            float s = 0.0f;
#pragma unroll
            for (int j = 0; j < 16; j++) { v[j] = expf(v[j] - m); s += v[j]; }
            s += __shfl_xor_sync(FULL, s, 1);
            s += __shfl_xor_sync(FULL, s, 2);
            float inv = 1.0f / s;
#pragma unroll
            for (int j = 0; j < 16; j++) v[j] *= inv;

            // write probs (quad covers 32B contiguous per ng)
            float* pr = probs_out + (size_t)row * E_DIM + 2 * qc;
#pragma unroll
            for (int ng = 0; ng < 8; ng++)
                *(float2*)(pr + 8 * ng) = make_float2(v[2 * ng], v[2 * ng + 1]);

            // local top-2 (ascending cols -> tie keeps lower index)
            float v1 = -1.0f, v2 = -1.0f;
            int i1 = 0, i2 = 0;
#pragma unroll
            for (int j = 0; j < 16; j++) {
                int c = 8 * (j >> 1) + 2 * qc + (j & 1);
                float val = v[j];
                if (val > v1)      { v2 = v1; i2 = i1; v1 = val; i1 = c; }
                else if (val > v2) { v2 = val; i2 = c; }
            }
            // quad merge (offsets 1, 2)
#pragma unroll
            for (int off = 1; off <= 2; off <<= 1) {
                float ov1 = __shfl_xor_sync(FULL, v1, off);
                int   oi1 = __shfl_xor_sync(FULL, i1, off);
                float ov2 = __shfl_xor_sync(FULL, v2, off);
                int   oi2 = __shfl_xor_sync(FULL, i2, off);
                bool of = (ov1 > v1) || (ov1 == v1 && oi1 < i1);
                float n1, n2; int ni1, ni2;
                if (of) {
                    n1 = ov1; ni1 = oi1;
                    bool aa = (v1 > ov2) || (v1 == ov2 && i1 < oi2);
                    if (aa) { n2 = v1;  ni2 = i1;  } else { n2 = ov2; ni2 = oi2; }
                } else {
                    n1 = v1; ni1 = i1;
                    bool aa = (ov1 > v2) || (ov1 == v2 && oi1 < i2);
                    if (aa) { n2 = ov1; ni2 = oi1; } else { n2 = v2;  ni2 = i2;  }
                }
                v1 = n1; i1 = ni1; v2 = n2; i2 = ni2;
            }

            // candidates 3,4: redo with top-2 masked out
            float v3 = -1.0f, v4 = -1.0f;
            int i3 = 0, i4 = 0;
#pragma unroll
            for (int j = 0; j < 16; j++) {
                int c = 8 * (j >> 1) + 2 * qc + (j & 1);
                float val = (c == i1 || c == i2) ? -1.0f : v[j];
                if (val > v3)      { v4 = v3; i4 = i3; v3 = val; i3 = c; }
                else if (val > v4) { v4 = val; i4 = c; }
            }
#pragma unroll
            for (int off = 1; off <= 2; off <<= 1) {
                float ov1 = __shfl_xor_sync(FULL, v3, off);
                int   oi1 = __shfl_xor_sync(FULL, i3, off);
                float ov2 = __shfl_xor_sync(FULL, v4, off);
                int   oi2 = __shfl_xor_sync(FULL, i4, off);
                bool of = (ov1 > v3) || (ov1 == v3 && oi1 < i3);
                float n1, n2; int ni1, ni2;
                if (of) {
                    n1 = ov1; ni1 = oi1;
                    bool aa = (v3 > ov2) || (v3 == ov2 && i3 < oi2);
                    if (aa) { n2 = v3;  ni2 = i3;  } else { n2 = ov2; ni2 = oi2; }
                } else {
                    n1 = v3; ni1 = i3;
                    bool aa = (ov1 > v4) || (ov1 == v4 && oi1 < i4);
                    if (aa) { n2 = ov1; ni2 = oi1; } else { n2 = v4;  ni2 = i4;  }
                }
                v3 = n1; i3 = ni1; v4 = n2; i4 = ni2;
            }

            bool amb = ((v1 - v2) < TAU) || ((v2 - v3) < TAU);

            if (!amb && qc == 0) {
                float denom = v1 + v2 + 1e-9f;
                idx_out[(size_t)row * 2 + 0] = (float)i1;
                idx_out[(size_t)row * 2 + 1] = (float)i2;
                w_out[(size_t)row * 2 + 0]   = v1 / denom;
                w_out[(size_t)row * 2 + 1]   = v2 / denom;
            }

            // rare exact refine, whole warp cooperates per flagged row
            unsigned bal = __ballot_sync(FULL, amb && qc == 0);
            while (bal) {
                int src = __ffs(bal) - 1;
                bal &= bal - 1;
                int rrow = __shfl_sync(FULL, row, src);
                int c0 = __shfl_sync(FULL, i1, src);
                int c1 = __shfl_sync(FULL, i2, src);
                int c2 = __shfl_sync(FULL, i3, src);
                int c3 = __shfl_sync(FULL, i4, src);

                const float* xrow = x + (size_t)rrow * D_DIM;
                const float* w0 = W + (size_t)c0 * D_DIM;
                const float* w1 = W + (size_t)c1 * D_DIM;
                const float* w2 = W + (size_t)c2 * D_DIM;
                const float* w3 = W + (size_t)c3 * D_DIM;

                float d0 = 0.f, d1 = 0.f, d2 = 0.f, d3 = 0.f;
                for (int kk = lane * 4; kk < D_DIM; kk += 128) {
                    float4 xv = *(const float4*)(xrow + kk);
                    float4 aa = *(const float4*)(w0 + kk);
                    float4 bb = *(const float4*)(w1 + kk);
                    float4 cc = *(const float4*)(w2 + kk);
                    float4 dd = *(const float4*)(w3 + kk);
                    d0 = fmaf(xv.x, aa.x, fmaf(xv.y, aa.y, fmaf(xv.z, aa.z, fmaf(xv.w, aa.w, d0))));
                    d1 = fmaf(xv.x, bb.x, fmaf(xv.y, bb.y, fmaf(xv.z, bb.z, fmaf(xv.w, bb.w, d1))));
                    d2 = fmaf(xv.x, cc.x, fmaf(xv.y, cc.y, fmaf(xv.z, cc.z, fmaf(xv.w, cc.w, d2))));
                    d3 = fmaf(xv.x, dd.x, fmaf(xv.y, dd.y, fmaf(xv.z, dd.z, fmaf(xv.w, dd.w, d3))));
                }
#pragma unroll
                for (int off = 16; off > 0; off >>= 1) {
                    d0 += __shfl_xor_sync(FULL, d0, off);
                    d1 += __shfl_xor_sync(FULL, d1, off);
                    d2 += __shfl_xor_sync(FULL, d2, off);
                    d3 += __shfl_xor_sync(FULL, d3, off);
                }
                if (lane == 0) {
                    float l[4]  = {d0, d1, d2, d3};
                    int   id[4] = {c0, c1, c2, c3};
#pragma unroll
                    for (int i = 0; i < 2; i++) {
                        int best = i;
#pragma unroll
                        for (int j = i + 1; j < 4; j++) {
                            if ((l[j] > l[best]) || (l[j] == l[best] && id[j] < id[best])) best = j;
                        }
                        float tl = l[i]; l[i] = l[best]; l[best] = tl;
                        int ti = id[i]; id[i] = id[best]; id[best] = ti;
                    }
                    float mm  = fmaxf(l[0], l[1]);
                    float ee1 = expf(l[0] - mm);
                    float ee2 = expf(l[1] - mm);
                    float w1v = ee1 / (ee1 + ee2);
                    idx_out[(size_t)rrow * 2 + 0] = (float)id[0];
                    idx_out[(size_t)rrow * 2 + 1] = (float)id[1];
                    w_out[(size_t)rrow * 2 + 0]   = w1v;
                    w_out[(size_t)rrow * 2 + 1]   = 1.0f - w1v;
                }
            }
        }
    }
}

extern "C" void kernel_launch(void* const* d_in, const int* in_sizes, int n_in,
                              void* d_out, int out_size)
{
    const float* x = (const float*)d_in[0];
    const float* W = (const float*)d_in[1];
    const int N = in_sizes[0] / D_DIM;   // 16384

    float* out   = (float*)d_out;
    float* probs = out;
    float* idx   = out + (size_t)N * E_DIM;
    float* wts   = out + (size_t)N * E_DIM + (size_t)N * 2;

    bprep_kernel<<<128, 256>>>(W);
    router_kernel<<<N / 32, 32>>>(x, W, probs, idx, wts);
}

// round 17
// speedup vs baseline: 1.6330x; 1.3020x over previous
#include <cuda_runtime.h>
#include <cuda_fp16.h>
#include <cstdint>
#include <math.h>

// Router: logits = x @ W^T (N=16384, D=2048, E=64), softmax, top-2, renorm.
// Output fp32 concat: probs [N*64] | indices [N*2] | weights [N*2]
//
// R17: split-K fused GEMM. 4096 independent warps (16 rows x 64 experts x
// 512 k-values each; 28 warps/SM vs R16's 3.5). Direct fp32 x reads,
// in-register fp16 conversion (R16-validated fragment math), L2-resident
// pre-fragmented W. Partial logits (fp32) to gmem; epilogue kernel sums 4
// partials, does softmax/top-2 (R13-validated warp code) + inline exact
// refine. x read exactly once.

#define D_DIM 2048
#define E_DIM 64
#define N_ROWS 16384
#define NKS (D_DIM / 16)       // 128 ksteps
#define SPLITK 4
#define KS_PER (NKS / SPLITK)  // 32
#define NT16 (N_ROWS / 16)     // 1024 tiles
#define TAU 2e-3f

__device__ uint2 g_Bf[NKS * 8 * 32];                       // W fragments (256 KB)
__device__ float g_part[(size_t)SPLITK * N_ROWS * E_DIM];  // 16 MB partials

__device__ __forceinline__ uint32_t h2pack(float a, float b) {
    __half2 h = __floats2half2_rn(a, b);
    return *(uint32_t*)&h;
}
__device__ __forceinline__ void mma_f16(float* c,
                                        uint32_t a0, uint32_t a1, uint32_t a2, uint32_t a3,
                                        uint32_t b0, uint32_t b1) {
    asm volatile(
        "mma.sync.aligned.m16n8k16.row.col.f32.f16.f16.f32 "
        "{%0,%1,%2,%3}, {%4,%5,%6,%7}, {%8,%9}, {%0,%1,%2,%3};"
        : "+f"(c[0]), "+f"(c[1]), "+f"(c[2]), "+f"(c[3])
        : "r"(a0), "r"(a1), "r"(a2), "r"(a3), "r"(b0), "r"(b1));
}

// ---- Kernel 1: W -> fragment order (validated R15/R16 layout) ----
__global__ __launch_bounds__(256, 4)
void bprep_kernel(const float* __restrict__ W)
{
    const int i = blockIdx.x * 256 + threadIdx.x;   // 0..32767
    const int k    = i >> 8;
    const int rem  = i & 255;
    const int ng   = rem >> 5;
    const int lane = rem & 31;
    const int qr   = lane >> 2;
    const int qc   = lane & 3;
    const int e    = ng * 8 + qr;
    const float* w = W + (size_t)e * D_DIM + k * 16;
    uint2 v;
    v.x = h2pack(w[2 * qc],     w[2 * qc + 1]);
    v.y = h2pack(w[2 * qc + 8], w[2 * qc + 9]);
    g_Bf[(k * 8 + ng) * 32 + lane] = v;
}

// ---- Kernel 2: split-K GEMM. 512 blocks x 256 thr = 4096 warps ----
__global__ __launch_bounds__(256, 4)
void gemm_kernel(const float* __restrict__ x)
{
    const int tid  = threadIdx.x;
    const int wid  = tid >> 5;
    const int lane = tid & 31;
    const int qr   = lane >> 2;
    const int qc   = lane & 3;

    const int idx = blockIdx.x * 8 + wid;   // 0..4095
    const int wt  = idx >> 2;               // 16-row tile 0..1023
    const int sp  = idx & 3;                // k split 0..3
    const int base = wt * 16;
    const int ks0  = sp * KS_PER;

    const float* p0 = x + (size_t)(base + qr) * D_DIM + 2 * qc;
    const float* p1 = p0 + (size_t)8 * D_DIM;

    float acc[8][4];
#pragma unroll
    for (int j = 0; j < 8; j++)
#pragma unroll
        for (int k = 0; k < 4; k++) acc[j][k] = 0.0f;

    const uint2* Bp = g_Bf + lane;

#pragma unroll 4
    for (int kk = 0; kk < KS_PER; kk++) {
        const int k  = ks0 + kk;
        const int ko = k * 16;

        float2 f00 = *(const float2*)(p0 + ko);
        float2 f01 = *(const float2*)(p0 + ko + 8);
        float2 f10 = *(const float2*)(p1 + ko);
        float2 f11 = *(const float2*)(p1 + ko + 8);
        uint32_t a0 = h2pack(f00.x, f00.y);
        uint32_t a1 = h2pack(f10.x, f10.y);
        uint32_t a2 = h2pack(f01.x, f01.y);
        uint32_t a3 = h2pack(f11.x, f11.y);

        uint2 b[8];
#pragma unroll
        for (int ng = 0; ng < 8; ng++)
            b[ng] = __ldg(Bp + (size_t)(k * 8 + ng) * 32);

#pragma unroll
        for (int ng = 0; ng < 8; ng++)
            mma_f16(acc[ng], a0, a1, a2, a3, b[ng].x, b[ng].y);
    }

    // store partials: lane owns rows (base+qr, base+8+qr), cols ng*8+2qc(+1)
    float* d0 = g_part + ((size_t)sp * N_ROWS + base + qr) * E_DIM + 2 * qc;
    float* d1 = g_part + ((size_t)sp * N_ROWS + base + 8 + qr) * E_DIM + 2 * qc;
#pragma unroll
    for (int ng = 0; ng < 8; ng++) {
        *(float2*)(d0 + 8 * ng) = make_float2(acc[ng][0], acc[ng][1]);
        *(float2*)(d1 + 8 * ng) = make_float2(acc[ng][2], acc[ng][3]);
    }
}

// ---- Kernel 3: epilogue. 2048 blocks x 256 thr; one warp per row ----
__global__ __launch_bounds__(256, 4)
void epi_kernel(const float* __restrict__ x,
                const float* __restrict__ W,
                float* __restrict__ probs_out,
                float* __restrict__ idx_out,
                float* __restrict__ w_out)
{
    const int tid  = threadIdx.x;
    const int wid  = tid >> 5;
    const int lane = tid & 31;
    const int row  = blockIdx.x * 8 + wid;
    const unsigned FULL = 0xFFFFFFFFu;

    // sum 4 partials; lane owns experts lane and lane+32
    float l1 = 0.0f, l2 = 0.0f;
#pragma unroll
    for (int sp = 0; sp < SPLITK; sp++) {
        const float* p = g_part + ((size_t)sp * N_ROWS + row) * E_DIM;
        l1 += p[lane];
        l2 += p[lane + 32];
    }

    float m = fmaxf(l1, l2);
#pragma unroll
    for (int off = 16; off > 0; off >>= 1)
        m = fmaxf(m, __shfl_xor_sync(FULL, m, off));

    float e1 = expf(l1 - m);
    float e2 = expf(l2 - m);

    float s = e1 + e2;
#pragma unroll
    for (int off = 16; off > 0; off >>= 1)
        s += __shfl_xor_sync(FULL, s, off);
    float inv = 1.0f / s;

    float pa = e1 * inv;
    float pb = e2 * inv;

    probs_out[(size_t)row * E_DIM + lane]      = pa;
    probs_out[(size_t)row * E_DIM + lane + 32] = pb;

    auto wtop2 = [&](float xa, int ia, float xb, int ib,
                     float& V1, int& I1, float& V2, int& I2) {
        float v1, v2; int i1, i2;
        if (xa >= xb) { v1 = xa; i1 = ia; v2 = xb; i2 = ib; }
        else          { v1 = xb; i1 = ib; v2 = xa; i2 = ia; }
#pragma unroll
        for (int off = 16; off > 0; off >>= 1) {
            float ov1 = __shfl_xor_sync(FULL, v1, off);
            int   oi1 = __shfl_xor_sync(FULL, i1, off);
            float ov2 = __shfl_xor_sync(FULL, v2, off);
            int   oi2 = __shfl_xor_sync(FULL, i2, off);
            bool of = (ov1 > v1) || (ov1 == v1 && oi1 < i1);
            float n1, n2; int ni1, ni2;
            if (of) {
                n1 = ov1; ni1 = oi1;
                bool aa = (v1 > ov2) || (v1 == ov2 && i1 < oi2);
                if (aa) { n2 = v1;  ni2 = i1;  } else { n2 = ov2; ni2 = oi2; }
            } else {
                n1 = v1; ni1 = i1;
                bool aa = (ov1 > v2) || (ov1 == v2 && oi1 < i2);
                if (aa) { n2 = ov1; ni2 = oi1; } else { n2 = v2;  ni2 = i2;  }
            }
            v1 = n1; i1 = ni1; v2 = n2; i2 = ni2;
        }
        V1 = v1; I1 = i1; V2 = v2; I2 = i2;
    };

    float v1, v2, v3, v4;
    int i1, i2, i3, i4;
    wtop2(pa, lane, pb, lane + 32, v1, i1, v2, i2);

    float pa2 = (lane == i1 || lane == i2) ? -1.0f : pa;
    float pb2 = (lane + 32 == i1 || lane + 32 == i2) ? -1.0f : pb;
    wtop2(pa2, lane, pb2, lane + 32, v3, i3, v4, i4);

    bool ambiguous = ((v1 - v2) < TAU) || ((v2 - v3) < TAU);

    if (!ambiguous) {
        if (lane == 0) {
            float denom = v1 + v2 + 1e-9f;
            idx_out[(size_t)row * 2 + 0] = (float)i1;
            idx_out[(size_t)row * 2 + 1] = (float)i2;
            w_out[(size_t)row * 2 + 0]   = v1 / denom;
            w_out[(size_t)row * 2 + 1]   = v2 / denom;
        }
    } else {
        // inline exact fp32 recompute of 4 candidate logits
        const float* xr = x + (size_t)row * D_DIM;
        const float* w0 = W + (size_t)i1 * D_DIM;
        const float* w1 = W + (size_t)i2 * D_DIM;
        const float* w2 = W + (size_t)i3 * D_DIM;
        const float* w3 = W + (size_t)i4 * D_DIM;

        float d0 = 0.f, d1 = 0.f, d2 = 0.f, d3 = 0.f;
        for (int k = lane * 4; k < D_DIM; k += 128) {
            float4 xv = *(const float4*)(xr + k);
            float4 a  = *(const float4*)(w0 + k);
            float4 b  = *(const float4*)(w1 + k);
            float4 cc = *(const float4*)(w2 + k);
            float4 dd = *(const float4*)(w3 + k);
            d0 = fmaf(xv.x, a.x,  fmaf(xv.y, a.y,  fmaf(xv.z, a.z,  fmaf(xv.w, a.w,  d0))));
            d1 = fmaf(xv.x, b.x,  fmaf(xv.y, b.y,  fmaf(xv.z, b.z,  fmaf(xv.w, b.w,  d1))));
            d2 = fmaf(xv.x, cc.x, fmaf(xv.y, cc.y, fmaf(xv.z, cc.z, fmaf(xv.w, cc.w, d2))));
            d3 = fmaf(xv.x, dd.x, fmaf(xv.y, dd.y, fmaf(xv.z, dd.z, fmaf(xv.w, dd.w, d3))));
        }
#pragma unroll
        for (int off = 16; off > 0; off >>= 1) {
            d0 += __shfl_xor_sync(FULL, d0, off);
            d1 += __shfl_xor_sync(FULL, d1, off);
            d2 += __shfl_xor_sync(FULL, d2, off);
            d3 += __shfl_xor_sync(FULL, d3, off);
        }
        if (lane == 0) {
            float l[4]  = {d0, d1, d2, d3};
            int   id[4] = {i1, i2, i3, i4};
#pragma unroll
            for (int i = 0; i < 2; i++) {
                int best = i;
#pragma unroll
                for (int j = i + 1; j < 4; j++) {
                    if ((l[j] > l[best]) || (l[j] == l[best] && id[j] < id[best])) best = j;
                }
                float tl = l[i]; l[i] = l[best]; l[best] = tl;
                int ti = id[i]; id[i] = id[best]; id[best] = ti;
            }
            float mm  = fmaxf(l[0], l[1]);
            float ee1 = expf(l[0] - mm);
            float ee2 = expf(l[1] - mm);
            float w1v = ee1 / (ee1 + ee2);
            idx_out[(size_t)row * 2 + 0] = (float)id[0];
            idx_out[(size_t)row * 2 + 1] = (float)id[1];
            w_out[(size_t)row * 2 + 0]   = w1v;
            w_out[(size_t)row * 2 + 1]   = 1.0f - w1v;
        }
    }
}

extern "C" void kernel_launch(void* const* d_in, const int* in_sizes, int n_in,
                              void* d_out, int out_size)
{
    const float* x = (const float*)d_in[0];
    const float* W = (const float*)d_in[1];
    const int N = in_sizes[0] / D_DIM;   // 16384

    float* out   = (float*)d_out;
    float* probs = out;
    float* idx   = out + (size_t)N * E_DIM;
    float* wts   = out + (size_t)N * E_DIM + (size_t)N * 2;

    bprep_kernel<<<128, 256>>>(W);
    gemm_kernel<<<(NT16 * SPLITK) / 8, 256>>>(x);
    epi_kernel<<<N / 8, 256>>>(x, W, probs, idx, wts);
}